// round 7
// baseline (speedup 1.0000x reference)
#include <cuda_runtime.h>
#include <cstdio>
#include <math.h>

// HMM forward, linear-domain, lagged rescale. 16 clusters x 8 CTAs.
// CTA owns 64-row slice of W = A^T + eps (fp32 smem), 4 batches per cluster.
// Per step: leader-warp mbar wait (RELAXED) -> bar -> per-warp x copy (L2) ->
// matvec (16 warps, f32x2 FFMA) -> bar -> epilogue u=z*e, x'=u/d -> bar ->
// publish maxes + parallel remote arrives (release). C += log d.
// Instrumented: tid0 accumulates per-phase clock deltas, printf at t=TT-1.

#define HH 512
#define VV 50257
#define TT 512
#define NT 512

using ull = unsigned long long;
using u32 = unsigned int;

#define CLUSTER_SYNC() do { \
  asm volatile("barrier.cluster.arrive.aligned;" ::: "memory"); \
  asm volatile("barrier.cluster.wait.aligned;"   ::: "memory"); \
} while (0)

__device__ float g_X[2][16][2048];        // [par][cluster][kp*8 + b*2 + hi]
__device__ float g_Max[2][16][8][4];      // [par][cluster][ctaRank][b]

__device__ __forceinline__ ull ffma2(ull a, ull b, ull c) {
  ull d;
  asm("fma.rn.f32x2 %0, %1, %2, %3;" : "=l"(d) : "l"(a), "l"(b), "l"(c));
  return d;
}
__device__ __forceinline__ float psum2(ull u) {
  return __uint_as_float((unsigned)u) + __uint_as_float((unsigned)(u >> 32));
}
__device__ __forceinline__ u32 smem_u32(const void* p) {
  u32 a;
  asm("{ .reg .u64 t; cvta.to.shared.u64 t, %1; cvt.u32.u64 %0, t; }" : "=r"(a) : "l"(p));
  return a;
}
__device__ __forceinline__ u32 mapa_u32(u32 local, int rank) {
  u32 r;
  asm("mapa.shared::cluster.u32 %0, %1, %2;" : "=r"(r) : "r"(local), "r"(rank));
  return r;
}
__device__ __forceinline__ void mbar_wait_relaxed(u32 addr, u32 ph) {
  asm volatile(
    "{\n\t.reg .pred P;\n\t"
    "W%=:\n\t"
    "mbarrier.try_wait.parity.relaxed.cta.shared::cta.b64 P, [%0], %1, 0x989680;\n\t"
    "@!P bra W%=;\n\t}"
    :: "r"(addr), "r"(ph) : "memory");
}
__device__ __forceinline__ u32 rclock() {
  u32 c;
  asm volatile("mov.u32 %0, %%clock;" : "=r"(c));
  return c;
}

extern __shared__ float sW[];   // 128KB: W pairs [kp:256][row:64][2]

__global__ void __cluster_dims__(8, 1, 1) __launch_bounds__(NT, 1)
hmm_main(const float* __restrict__ A, const float* __restrict__ beta,
         const float* __restrict__ gamma, const int* __restrict__ ids,
         float* __restrict__ out) {
  __shared__ __align__(16) float  xs[2048];     // x vec, [kp*8 + b*2 + hi]
  __shared__ __align__(16) float4 red[16][64];  // [warp][row] 4-batch partials
  __shared__ int    sids[4][TT];
  __shared__ float  sm[8];                      // act-warp maxes
  __shared__ float  smax2[16];
  __shared__ __align__(8) ull mbar;

  const int tid  = threadIdx.x;
  const int myq  = blockIdx.x & 7;
  const int cl   = blockIdx.x >> 3;
  const int base = myq * 64;
  const int warp = tid >> 5, lane = tid & 31;

  // ---- prologue: W slice into smem ----
  for (int idx = tid; idx < 64 * HH; idx += NT) {
    int c = idx & 63, j = idx >> 6;
    sW[(j >> 1) * 128 + c * 2 + (j & 1)] = A[j * HH + base + c] + 1e-12f;
  }
  for (int i = tid; i < 4 * TT; i += NT) {
    int b0 = i >> 9, t0 = i & (TT - 1);
    sids[b0][t0] = ids[(cl * 4 + b0) * TT + t0];
  }
  if (tid == 0)
    asm volatile("mbarrier.init.shared.b64 [%0], %1;"
                 :: "r"(smem_u32(&mbar)), "r"(8u) : "memory");
  __syncthreads();

  // ---- init: full alpha0, M0, x1 (rank 0 publishes) ----
  float M0[4];
  {
    float* a0s = (float*)red;   // 2048 scratch
    for (int idx = tid; idx < 4 * HH; idx += NT) {
      int bb = idx >> 9, k = idx & 511;
      a0s[idx] = __logf(gamma[k]) + __ldg(&beta[(size_t)k * VV + sids[bb][0]]);
    }
    __syncthreads();
    {
      int bb = warp >> 2, seg = warp & 3;
      float m = -3.4e38f;
      #pragma unroll
      for (int i = 0; i < 4; i++)
        m = fmaxf(m, a0s[bb * 512 + seg * 128 + i * 32 + lane]);
      #pragma unroll
      for (int o = 16; o > 0; o >>= 1)
        m = fmaxf(m, __shfl_xor_sync(0xffffffffu, m, o));
      if (lane == 0) smax2[warp] = m;
    }
    __syncthreads();
    #pragma unroll
    for (int bb = 0; bb < 4; bb++)
      M0[bb] = fmaxf(fmaxf(smax2[4 * bb], smax2[4 * bb + 1]),
                     fmaxf(smax2[4 * bb + 2], smax2[4 * bb + 3]));
    if (myq == 0) {
      for (int idx = tid; idx < 4 * HH; idx += NT) {
        int bb = idx >> 9, k = idx & 511;
        __stcg(&g_X[1][cl][(k >> 1) * 8 + bb * 2 + (k & 1)],
               __expf(a0s[idx] - M0[bb]));
      }
    }
    __syncthreads();
  }
  CLUSTER_SYNC();

  const bool act = (tid < 256);
  const int  b   = (tid >> 6) & 3;
  const int  r   = tid & 63;
  const int  h   = base + r;
  float C = M0[b];
  const u32 mbar_a = smem_u32(&mbar);
  u32 wph = 0;

  // timing accumulators (tid0 only meaningfully updated)
  ull s_wait = 0, s_rel = 0, s_mv = 0, s_epi = 0, s_pub = 0;
  u32 c0 = 0, c1, c2, c3, c4;
  const bool tim = (tid == 0);

  for (int t = 1; t < TT; t++) {
    const int par = t & 1;
    if (tim) c0 = rclock();

    float bsel = 0.0f;
    if (act) bsel = __ldg(&beta[(size_t)h * VV + sids[b][t]]);

    // leader-warp-only wait, relaxed (no acquire -> no L1 flush path)
    if (t >= 2) {
      if (warp == 0 && lane == 0) mbar_wait_relaxed(mbar_a, wph);
      wph ^= 1;
    }
    if (tim) { c1 = rclock(); s_wait += (u32)(c1 - c0); }
    __syncthreads();                       // release all warps
    if (tim) { c2 = rclock(); s_rel += (u32)(c2 - c1); }

    float d = 1.0f;
    if (t >= 2 && act) {
      const float* gm = &g_Max[par][cl][0][b];
      d = __ldcg(&gm[0]);
      #pragma unroll
      for (int q = 1; q < 8; q++) d = fmaxf(d, __ldcg(&gm[q * 4]));
    }

    // per-warp x copy: warp copies exactly the 512B it will read
    {
      const float4* src = (const float4*)&g_X[par][cl][0];
      float4 v = __ldcg(src + warp * 32 + lane);
      *(float4*)(xs + (warp * 32 + lane) * 4) = v;
      __syncwarp();
    }

    // matvec: warp owns kp in [16*warp, 16*warp+16); rows {lane, lane+32}, 4 b
    ull a0 = 0, a1 = 0, a2 = 0, a3 = 0, a4 = 0, a5 = 0, a6 = 0, a7 = 0;
    {
      const ull* wp = (const ull*)sW + warp * (16 * 64) + lane;
      const ulonglong2* xp = (const ulonglong2*)xs + warp * 32;
      #pragma unroll
      for (int kpi = 0; kpi < 16; kpi++) {
        ull w0 = wp[0];
        ull w1 = wp[32];
        ulonglong2 xa = xp[0];   // batches 0,1
        ulonglong2 xb = xp[1];   // batches 2,3
        wp += 64; xp += 2;
        a0 = ffma2(w0, xa.x, a0);
        a1 = ffma2(w0, xa.y, a1);
        a2 = ffma2(w0, xb.x, a2);
        a3 = ffma2(w0, xb.y, a3);
        a4 = ffma2(w1, xa.x, a4);
        a5 = ffma2(w1, xa.y, a5);
        a6 = ffma2(w1, xb.x, a6);
        a7 = ffma2(w1, xb.y, a7);
      }
    }
    red[warp][lane]      = make_float4(psum2(a0), psum2(a1), psum2(a2), psum2(a3));
    red[warp][lane + 32] = make_float4(psum2(a4), psum2(a5), psum2(a6), psum2(a7));
    __syncthreads();
    if (tim) { c3 = rclock(); s_mv += (u32)(c3 - c2); }

    if (act) {
      const float* rp = (const float*)red + r * 4 + b;
      float z = rp[0];
      #pragma unroll
      for (int w = 1; w < 16; w++) z += rp[w * 256];
      float u = z * __expf(bsel);

      if (t == TT - 1) {
        out[(cl * 4 + b) * HH + h] = __logf(u) + C;
      } else {
        __stcg(&g_X[par ^ 1][cl][(h >> 1) * 8 + b * 2 + (h & 1)],
               u * __frcp_rn(d));
        float lm = u;
        #pragma unroll
        for (int o = 16; o > 0; o >>= 1)
          lm = fmaxf(lm, __shfl_xor_sync(0xffffffffu, lm, o));
        if (lane == 0) sm[warp] = lm;
        C += __logf(d);
      }
    }
    __syncthreads();
    if (tim) { c4 = rclock(); s_epi += (u32)(c4 - c3); }

    if (t < TT - 1) {
      if (warp == 0) {
        if (lane < 4)
          __stcg(&g_Max[par ^ 1][cl][myq][lane],
                 fmaxf(sm[2 * lane], sm[2 * lane + 1]));
        __syncwarp();
        if (lane < 8) {     // parallel remote arrives, one rank per lane
          u32 ra = mapa_u32(mbar_a, lane);
          asm volatile("mbarrier.arrive.release.cluster.shared::cluster.b64 _, [%0];"
                       :: "r"(ra) : "memory");
        }
      }
      if (tim) s_pub += (u32)(rclock() - c4);
    } else if (tim && (blockIdx.x == 0 || blockIdx.x == 9)) {
      printf("PHASES cta=%d wait=%llu rel=%llu mv=%llu epi=%llu pub=%llu\n",
             (int)blockIdx.x, s_wait, s_rel, s_mv, s_epi, s_pub);
    }
  }
}

extern "C" void kernel_launch(void* const* d_in, const int* in_sizes, int n_in,
                              void* d_out, int out_size) {
  const float* A     = (const float*)d_in[0];   // alpha_exp (H,H)
  const float* beta  = (const float*)d_in[1];   // (H,V)
  const float* gamma = (const float*)d_in[2];   // (1,H)
  const int*   ids   = (const int*)d_in[3];     // (B,T) int32
  float* out = (float*)d_out;                   // (B,H) f32

  cudaFuncSetAttribute(hmm_main, cudaFuncAttributeMaxDynamicSharedMemorySize,
                       132 * 1024);
  hmm_main<<<128, NT, 131072>>>(A, beta, gamma, ids, out);
}

// round 8
// speedup vs baseline: 1.4526x; 1.4526x over previous
#include <cuda_runtime.h>
#include <math.h>

// HMM forward, linear domain, power-of-2 lagged rescale, NO cross-CTA max
// exchange. 16 clusters x 8 CTAs; cluster owns 4 batches; CTA owns a 64-row
// slice of W = A^T + eps (fp32, smem-resident). Per step:
//   relaxed mbar wait -> copy full u (L2, per-warp 512B) + local per-batch max
//   -> matvec (16 warps, f32x2 FFMA) -> bar -> epilogue u'=z*e*2^-m (exact),
//   Cexp += m (int) -> bar -> 8 parallel remote release-arrives.
// exp(beta) for step t+1 gathered+computed during step t. log only at t=T-1.

#define HH 512
#define VV 50257
#define TT 512
#define NT 512

using ull = unsigned long long;
using u32 = unsigned int;

#define CLUSTER_SYNC() do { \
  asm volatile("barrier.cluster.arrive.aligned;" ::: "memory"); \
  asm volatile("barrier.cluster.wait.aligned;"   ::: "memory"); \
} while (0)

__device__ float g_X[2][16][2048];     // [par][cluster][kp*8 + b*2 + hi]

__device__ __forceinline__ ull ffma2(ull a, ull b, ull c) {
  ull d;
  asm("fma.rn.f32x2 %0, %1, %2, %3;" : "=l"(d) : "l"(a), "l"(b), "l"(c));
  return d;
}
__device__ __forceinline__ float psum2(ull u) {
  return __uint_as_float((unsigned)u) + __uint_as_float((unsigned)(u >> 32));
}
__device__ __forceinline__ u32 smem_u32(const void* p) {
  u32 a;
  asm("{ .reg .u64 t; cvta.to.shared.u64 t, %1; cvt.u32.u64 %0, t; }" : "=r"(a) : "l"(p));
  return a;
}
__device__ __forceinline__ u32 mapa_u32(u32 local, int rank) {
  u32 r;
  asm("mapa.shared::cluster.u32 %0, %1, %2;" : "=r"(r) : "r"(local), "r"(rank));
  return r;
}
__device__ __forceinline__ void mbar_wait_relaxed(u32 addr, u32 ph) {
  asm volatile(
    "{\n\t.reg .pred P;\n\t"
    "W%=:\n\t"
    "mbarrier.try_wait.parity.relaxed.cta.shared::cta.b64 P, [%0], %1, 0x989680;\n\t"
    "@!P bra W%=;\n\t}"
    :: "r"(addr), "r"(ph) : "memory");
}

extern __shared__ float sW[];   // 128KB: W pairs [kp:256][row:64][2]

__global__ void __cluster_dims__(8, 1, 1) __launch_bounds__(NT, 1)
hmm_main(const float* __restrict__ A, const float* __restrict__ beta,
         const float* __restrict__ gamma, const int* __restrict__ ids,
         float* __restrict__ out) {
  __shared__ __align__(16) float  xs[2048];     // x vec [kp*8 + b*2 + hi]
  __shared__ __align__(16) float4 red[16][64];  // [warp][row] 4-batch partials
  __shared__ float  wmx[16][4];                 // per-warp per-batch |u| max
  __shared__ int    sids[4][TT];
  __shared__ float  smax2[16];
  __shared__ __align__(8) ull mbar;

  const int tid  = threadIdx.x;
  const int myq  = blockIdx.x & 7;
  const int cl   = blockIdx.x >> 3;
  const int base = myq * 64;
  const int warp = tid >> 5, lane = tid & 31;

  // ---- prologue: W slice into smem ----
  for (int idx = tid; idx < 64 * HH; idx += NT) {
    int c = idx & 63, j = idx >> 6;
    sW[(j >> 1) * 128 + c * 2 + (j & 1)] = A[j * HH + base + c] + 1e-12f;
  }
  for (int i = tid; i < 4 * TT; i += NT) {
    int b0 = i >> 9, t0 = i & (TT - 1);
    sids[b0][t0] = ids[(cl * 4 + b0) * TT + t0];
  }
  if (tid == 0)
    asm volatile("mbarrier.init.shared.b64 [%0], %1;"
                 :: "r"(smem_u32(&mbar)), "r"(8u) : "memory");
  __syncthreads();

  // ---- init: full alpha0, M0, x1 = exp(alpha0 - M0) (rank 0 publishes) ----
  float M0[4];
  {
    float* a0s = (float*)red;   // 2048 scratch
    for (int idx = tid; idx < 4 * HH; idx += NT) {
      int bb = idx >> 9, k = idx & 511;
      a0s[idx] = __logf(gamma[k]) + __ldg(&beta[(size_t)k * VV + sids[bb][0]]);
    }
    __syncthreads();
    {
      int bb = warp >> 2, seg = warp & 3;
      float m = -3.4e38f;
      #pragma unroll
      for (int i = 0; i < 4; i++)
        m = fmaxf(m, a0s[bb * 512 + seg * 128 + i * 32 + lane]);
      #pragma unroll
      for (int o = 16; o > 0; o >>= 1)
        m = fmaxf(m, __shfl_xor_sync(0xffffffffu, m, o));
      if (lane == 0) smax2[warp] = m;
    }
    __syncthreads();
    #pragma unroll
    for (int bb = 0; bb < 4; bb++)
      M0[bb] = fmaxf(fmaxf(smax2[4 * bb], smax2[4 * bb + 1]),
                     fmaxf(smax2[4 * bb + 2], smax2[4 * bb + 3]));
    if (myq == 0) {
      for (int idx = tid; idx < 4 * HH; idx += NT) {
        int bb = idx >> 9, k = idx & 511;
        __stcg(&g_X[1][cl][(k >> 1) * 8 + bb * 2 + (k & 1)],
               __expf(a0s[idx] - M0[bb]));
      }
    }
    __syncthreads();
  }
  CLUSTER_SYNC();

  const bool act = (tid < 256);
  const int  b   = (tid >> 6) & 3;
  const int  r   = tid & 63;
  const int  h   = base + r;
  const float C0 = M0[b];
  int Cexp = 0;
  const u32 mbar_a = smem_u32(&mbar);
  u32 wph = 0;

  // emission pipeline: e_cur ready for t=1
  float e_cur = 0.0f;
  if (act) e_cur = __expf(__ldg(&beta[(size_t)h * VV + sids[b][1]]));

  for (int t = 1; t < TT; t++) {
    const int par = t & 1;

    // gather emission logit for t+1 (full step of latency slack)
    float bsel_next = 0.0f;
    if (act && t + 1 < TT)
      bsel_next = __ldg(&beta[(size_t)h * VV + sids[b][t + 1]]);

    if (t >= 2) { mbar_wait_relaxed(mbar_a, wph); wph ^= 1; }

    // copy full u_{t-1}: warp copies its own 512B; fold per-batch max
    {
      const float4* src = (const float4*)&g_X[par][cl][0];
      float4 v = __ldcg(src + warp * 32 + lane);
      *(float4*)(xs + (warp * 32 + lane) * 4) = v;
      // even lanes hold batches (0,1); odd lanes hold (2,3)
      float mlo = fmaxf(v.x, v.y);
      float mhi = fmaxf(v.z, v.w);
      #pragma unroll
      for (int o = 2; o <= 16; o <<= 1) {
        mlo = fmaxf(mlo, __shfl_xor_sync(0xffffffffu, mlo, o));
        mhi = fmaxf(mhi, __shfl_xor_sync(0xffffffffu, mhi, o));
      }
      if (lane == 0) { wmx[warp][0] = mlo; wmx[warp][1] = mhi; }
      if (lane == 1) { wmx[warp][2] = mlo; wmx[warp][3] = mhi; }
      __syncwarp();
    }

    // matvec: warp owns kp in [16*warp, 16*warp+16); rows {lane, lane+32}, 4 b
    ull a0 = 0, a1 = 0, a2 = 0, a3 = 0, a4 = 0, a5 = 0, a6 = 0, a7 = 0;
    {
      const ull* wp = (const ull*)sW + warp * (16 * 64) + lane;
      const ulonglong2* xp = (const ulonglong2*)xs + warp * 32;
      #pragma unroll
      for (int kpi = 0; kpi < 16; kpi++) {
        ull w0 = wp[0];
        ull w1 = wp[32];
        ulonglong2 xa = xp[0];   // batches 0,1
        ulonglong2 xb = xp[1];   // batches 2,3
        wp += 64; xp += 2;
        a0 = ffma2(w0, xa.x, a0);
        a1 = ffma2(w0, xa.y, a1);
        a2 = ffma2(w0, xb.x, a2);
        a3 = ffma2(w0, xb.y, a3);
        a4 = ffma2(w1, xa.x, a4);
        a5 = ffma2(w1, xa.y, a5);
        a6 = ffma2(w1, xb.x, a6);
        a7 = ffma2(w1, xb.y, a7);
      }
    }
    red[warp][lane]      = make_float4(psum2(a0), psum2(a1), psum2(a2), psum2(a3));
    red[warp][lane + 32] = make_float4(psum2(a4), psum2(a5), psum2(a6), psum2(a7));
    __syncthreads();

    if (act) {
      const float* rp = (const float*)red + r * 4 + b;
      float z = rp[0];
      #pragma unroll
      for (int w = 1; w < 16; w++) z += rp[w * 256];

      // local (redundant, cluster-consistent) per-batch scale: power of 2
      float M = wmx[0][b];
      #pragma unroll
      for (int w = 1; w < 16; w++) M = fmaxf(M, wmx[w][b]);
      int eb = (int)(__float_as_uint(M) >> 23);           // biased exponent
      float invM = __uint_as_float((u32)(254 - eb) << 23); // exact 2^(127-eb)
      Cexp += eb - 127;

      float u = z * e_cur * invM;

      if (t == TT - 1) {
        double o = (double)__logf(u) + (double)C0
                 + (double)Cexp * 0.6931471805599453;
        out[(cl * 4 + b) * HH + h] = (float)o;
      } else {
        __stcg(&g_X[par ^ 1][cl][(h >> 1) * 8 + b * 2 + (h & 1)], u);
        e_cur = __expf(bsel_next);   // off critical path
      }
    }
    __syncthreads();

    if (t < TT - 1 && warp == 0 && lane < 8) {
      u32 ra = mapa_u32(mbar_a, lane);   // parallel remote arrives
      asm volatile("mbarrier.arrive.release.cluster.shared::cluster.b64 _, [%0];"
                   :: "r"(ra) : "memory");
    }
  }
}

extern "C" void kernel_launch(void* const* d_in, const int* in_sizes, int n_in,
                              void* d_out, int out_size) {
  const float* A     = (const float*)d_in[0];   // alpha_exp (H,H)
  const float* beta  = (const float*)d_in[1];   // (H,V)
  const float* gamma = (const float*)d_in[2];   // (1,H)
  const int*   ids   = (const int*)d_in[3];     // (B,T) int32
  float* out = (float*)d_out;                   // (B,H) f32

  cudaFuncSetAttribute(hmm_main, cudaFuncAttributeMaxDynamicSharedMemorySize,
                       132 * 1024);
  hmm_main<<<128, NT, 131072>>>(A, beta, gamma, ids, out);
}